// round 12
// baseline (speedup 1.0000x reference)
#include <cuda_runtime.h>
#include <cuda_fp16.h>
#include <math.h>
#include <cstdint>

// Problem constants
#define Bn 2
#define Sn 2048
#define En 2048
#define NQ 16
#define NKV 4
#define HD 128
#define WINDOW 512
#define Mrows (Bn*Sn)          // 4096

// ---------------------------------------------------------------------------
// Scratch (device globals; no allocation allowed)
// ---------------------------------------------------------------------------
__device__ __half g_xf[(size_t)Mrows * En];        // x fp16
__device__ __half g_of[(size_t)Mrows * En];        // attention out fp16
__device__ __half g_wqkv[(size_t)3072 * 2048];     // [Wq|Wk|Wv] transposed [N,K]
__device__ __half g_wo[(size_t)2048 * 2048];
__device__ float  g_bqkv[3072];                    // [bq|bk|bv]
__device__ float2 g_rope[(size_t)Sn * 64];         // (cos,sin) per (pos,d)
// attention operands (written directly by GEMM epilogues)
__device__ __half g_qf16[(size_t)Mrows * NQ * HD]; // rope'd, scaled
__device__ __half g_kf16[(size_t)Mrows * NKV * HD];// rope'd
__device__ __half g_vf16[(size_t)Mrows * NKV * HD];

// ---------------------------------------------------------------------------
// PTX helpers
// ---------------------------------------------------------------------------
__device__ __forceinline__ uint32_t smem_to_u32(const void* p) {
    uint32_t a;
    asm("{ .reg .u64 t; cvta.to.shared.u64 t, %1; cvt.u32.u64 %0, t; }" : "=r"(a) : "l"(p));
    return a;
}
__device__ __forceinline__ void ldsm4(uint32_t* r, uint32_t addr) {
    asm volatile("ldmatrix.sync.aligned.m8n8.x4.shared.b16 {%0,%1,%2,%3}, [%4];"
        : "=r"(r[0]), "=r"(r[1]), "=r"(r[2]), "=r"(r[3]) : "r"(addr));
}
__device__ __forceinline__ void ldsm4t(uint32_t* r, uint32_t addr) {
    asm volatile("ldmatrix.sync.aligned.m8n8.x4.trans.shared.b16 {%0,%1,%2,%3}, [%4];"
        : "=r"(r[0]), "=r"(r[1]), "=r"(r[2]), "=r"(r[3]) : "r"(addr));
}
__device__ __forceinline__ void hmma16(float* c, const uint32_t* a, const uint32_t* b) {
    asm volatile("mma.sync.aligned.m16n8k16.row.col.f32.f16.f16.f32 "
        "{%0,%1,%2,%3}, {%4,%5,%6,%7}, {%8,%9}, {%0,%1,%2,%3};"
        : "+f"(c[0]), "+f"(c[1]), "+f"(c[2]), "+f"(c[3])
        : "r"(a[0]), "r"(a[1]), "r"(a[2]), "r"(a[3]), "r"(b[0]), "r"(b[1]));
}
__device__ __forceinline__ void cpa16(uint32_t dst, const void* src) {
    asm volatile("cp.async.cg.shared.global [%0], [%1], 16;" :: "r"(dst), "l"(src));
}
#define CP_COMMIT() asm volatile("cp.async.commit_group;" ::: "memory")
#define CP_WAIT0()  asm volatile("cp.async.wait_group 0;" ::: "memory")
#define CP_WAIT1()  asm volatile("cp.async.wait_group 1;" ::: "memory")

__device__ __forceinline__ uint32_t pack_h2(float a, float b) {
    __half2 v = __floats2half2_rn(a, b);
    return *(uint32_t*)&v;
}

// q scale: (1/sqrt(128)) * log2(e)  — softmax done in exp2 space
#define QSCALE 0.1275174056563446f
#define LOG2_10000 13.287712379549449f

// ---------------------------------------------------------------------------
// fp32 -> fp16, 4 elems/thread.
// ---------------------------------------------------------------------------
__global__ void cvt_f16(const float4* __restrict__ in, uint2* __restrict__ out, int n4)
{
    int i = blockIdx.x * blockDim.x + threadIdx.x;
    if (i >= n4) return;
    float4 v = in[i];
    __half2 a = __floats2half2_rn(v.x, v.y);
    __half2 b = __floats2half2_rn(v.z, v.w);
    uint2 o; o.x = *(uint32_t*)&a; o.y = *(uint32_t*)&b;
    out[i] = o;
}

// ---------------------------------------------------------------------------
// All weight transposes in one kernel. z selects the weight.
// ---------------------------------------------------------------------------
__global__ void cvt_w(const float* __restrict__ Wq, const float* __restrict__ Wk,
                      const float* __restrict__ Wv, const float* __restrict__ Wo,
                      __half* __restrict__ wqkv, __half* __restrict__ wo)
{
    const int z = blockIdx.z;
    const float* src; __half* dst; int N;
    if (z == 0)      { src = Wq; dst = wqkv;                       N = 2048; }
    else if (z == 1) { src = Wk; dst = wqkv + (size_t)2048 * 2048; N = 512; }
    else if (z == 2) { src = Wv; dst = wqkv + (size_t)2560 * 2048; N = 512; }
    else             { src = Wo; dst = wo;                          N = 2048; }
    const int n0 = blockIdx.x * 32;
    if (n0 >= N) return;
    const int k0 = blockIdx.y * 32;   // K = 2048 always
    __shared__ float t[32][33];
    const int tx = threadIdx.x, ty = threadIdx.y;
    #pragma unroll
    for (int j = ty; j < 32; j += 8)
        t[j][tx] = src[(size_t)(k0 + j) * N + n0 + tx];
    __syncthreads();
    #pragma unroll
    for (int j = ty; j < 32; j += 8)
        dst[(size_t)(n0 + j) * 2048 + k0 + tx] = __float2half(t[tx][j]);
}

// ---------------------------------------------------------------------------
// Build rope table (cos,sin) for (pos, d) and concat biases.
// ---------------------------------------------------------------------------
__global__ void build_tbl(float2* __restrict__ tbl,
                          const float* __restrict__ bq, const float* __restrict__ bk,
                          const float* __restrict__ bv, float* __restrict__ bqkv)
{
    int i = blockIdx.x * 256 + threadIdx.x;     // 131072 threads
    int d = i & 63, pos = i >> 6;
    float freq = exp2f(-((float)(2 * d) / 128.0f) * LOG2_10000);
    float ang = (float)pos * freq;
    tbl[i] = make_float2(cosf(ang), sinf(ang));
    if (i < 3072) {
        float b;
        if (i < 2048) b = bq[i];
        else if (i < 2560) b = bk[i - 2048];
        else b = bv[i - 2560];
        bqkv[i] = b;
    }
}

// ---------------------------------------------------------------------------
// fp16 HMMA GEMM, persistent tiles + R11's exact 2-stage inner loop.
// BM=128 BN=128 BK=64, 256 thr, 2 CTAs/SM.
//   MODE 0: C fp32 = A@B^T + bias                       (output projection)
//   MODE 1: fused QKV epilogue (rope LUT; regions CTA-uniform by col)
// ---------------------------------------------------------------------------
#define STG 32768
#define GEMM_SMEM (2*STG)

template<int MODE>
__global__ __launch_bounds__(256, 2)
void gemm_f16(const __half* __restrict__ A, const __half* __restrict__ B,
              const float* __restrict__ bias, float* __restrict__ C,
              __half* __restrict__ QF, __half* __restrict__ KF, __half* __restrict__ VF,
              const float2* __restrict__ rope,
              int M, int N, int K)
{
    extern __shared__ char smem[];
    const uint32_t sb = smem_to_u32(smem);
    const int tid = threadIdx.x;
    const int wid = tid >> 5;
    const int lane = tid & 31;
    const int wm = wid >> 1;
    const int wn = wid & 1;

    const int ld_row = tid >> 3;
    const int ld_seg = tid & 7;

    const int iters = K >> 6;
    const int ntN = N >> 7;
    const int ntiles = (M >> 7) * ntN;

    auto issueT = [&](int row0, int col0, int it, int stage) {
        const size_t kk = (size_t)(it << 6) + (ld_seg << 3);
        const uint32_t s0 = sb + stage * STG;
        #pragma unroll
        for (int j = 0; j < 4; ++j) {
            const int row = ld_row + j * 32;
            uint32_t bo = (uint32_t)(row * 128 + ld_seg * 16);
            uint32_t sw = bo ^ ((bo >> 3) & 0x70);
            cpa16(s0 + sw,         A + (size_t)(row0 + row) * K + kk);
            cpa16(s0 + 16384 + sw, B + (size_t)(col0 + row) * K + kk);
        }
        CP_COMMIT();
    };

    const int sub = lane >> 3;
    const int rr  = lane & 7;
    const int arow[2] = { wm*32 + 0*16 + (sub & 1)*8 + rr,
                          wm*32 + 1*16 + (sub & 1)*8 + rr };
    const int acol = (sub >> 1) * 16;
    const int brow[4] = { wn*64 + 0*16 + (sub >> 1)*8 + rr,
                          wn*64 + 1*16 + (sub >> 1)*8 + rr,
                          wn*64 + 2*16 + (sub >> 1)*8 + rr,
                          wn*64 + 3*16 + (sub >> 1)*8 + rr };
    const int bcol = (sub & 1) * 16;
    const int g = lane >> 2, t4 = lane & 3;

    // prime first tile
    {
        int t0 = blockIdx.x;
        if (t0 < ntiles) {
            const int r0 = (t0 / ntN) << 7, c0 = (t0 % ntN) << 7;
            issueT(r0, c0, 0, 0);
        }
    }

    for (int tile = blockIdx.x; tile < ntiles; tile += gridDim.x) {
        const int row0 = (tile / ntN) << 7;
        const int col0 = (tile % ntN) << 7;

        float acc[2][8][4];
        #pragma unroll
        for (int a = 0; a < 2; ++a)
            #pragma unroll
            for (int b = 0; b < 8; ++b)
                #pragma unroll
                for (int c = 0; c < 4; ++c) acc[a][b][c] = 0.f;

        // ---- R11 inner loop, verbatim ----
        for (int it = 0; it < iters; ++it) {
            const int stage = it & 1;
            if (it + 1 < iters) { issueT(row0, col0, it + 1, stage ^ 1); CP_WAIT1(); }
            else                { CP_WAIT0(); }
            __syncthreads();

            const uint32_t sA = sb + stage * STG;
            const uint32_t sB = sA + 16384;

            #pragma unroll
            for (int ks = 0; ks < 4; ++ks) {
                uint32_t af[2][4], bf[4][4];
                #pragma unroll
                for (int mi = 0; mi < 2; ++mi) {
                    uint32_t off = (uint32_t)(arow[mi] * 128 +
                                   ((ks*32 + acol) ^ ((arow[mi] & 7) << 4)));
                    ldsm4(af[mi], sA + off);
                }
                #pragma unroll
                for (int p = 0; p < 4; ++p) {
                    uint32_t off = (uint32_t)(brow[p] * 128 +
                                   ((ks*32 + bcol) ^ ((brow[p] & 7) << 4)));
                    ldsm4(bf[p], sB + off);
                }
                #pragma unroll
                for (int mi = 0; mi < 2; ++mi)
                    #pragma unroll
                    for (int ni = 0; ni < 8; ++ni)
                        hmma16(acc[mi][ni], af[mi], &bf[ni >> 1][(ni & 1) * 2]);
            }
            __syncthreads();
        }

        // Prologue of next tile overlaps with epilogue (stage 0 is free:
        // its last compute finished before the final iteration's syncs).
        const int nxt = tile + gridDim.x;
        if (nxt < ntiles) {
            const int nr = (nxt / ntN) << 7, nc = (nxt % ntN) << 7;
            issueT(nr, nc, 0, 0);
        }

        // Epilogue
        #pragma unroll
        for (int mi = 0; mi < 2; ++mi) {
            const int rlo = row0 + wm*32 + mi*16 + g;
            #pragma unroll
            for (int ni = 0; ni < 8; ++ni) {
                const int col = col0 + wn*64 + ni*8 + 2*t4;   // even
                const float b0 = bias[col], b1 = bias[col + 1];
                float v0a = acc[mi][ni][0] + b0, v1a = acc[mi][ni][1] + b1; // row rlo
                float v0b = acc[mi][ni][2] + b0, v1b = acc[mi][ni][3] + b1; // row rlo+8

                if (MODE == 0) {
                    *(float2*)(C + (size_t)rlo * N + col)       = make_float2(v0a, v1a);
                    *(float2*)(C + (size_t)(rlo + 8) * N + col) = make_float2(v0b, v1b);
                } else {
                    if (col < 2048) {               // Q: rope + scale -> fp16
                        const int d = (col & 127) >> 1;
                        #pragma unroll
                        for (int rsel = 0; rsel < 2; ++rsel) {
                            const int row = rlo + rsel * 8;
                            const float2 cs = rope[(size_t)(row & (Sn-1)) * 64 + d];
                            float e = rsel ? v0b : v0a, o = rsel ? v1b : v1a;
                            float r0 = (e * cs.x - o * cs.y) * QSCALE;
                            float r1 = (e * cs.y + o * cs.x) * QSCALE;
                            ((uint32_t*)QF)[((size_t)row * 2048 + col) >> 1] = pack_h2(r0, r1);
                        }
                    } else if (col < 2560) {        // K: rope -> fp16
                        const int kcol = col - 2048;
                        const int d = (kcol & 127) >> 1;
                        #pragma unroll
                        for (int rsel = 0; rsel < 2; ++rsel) {
                            const int row = rlo + rsel * 8;
                            const float2 cs = rope[(size_t)(row & (Sn-1)) * 64 + d];
                            float e = rsel ? v0b : v0a, o = rsel ? v1b : v1a;
                            float r0 = e * cs.x - o * cs.y;
                            float r1 = e * cs.y + o * cs.x;
                            ((uint32_t*)KF)[((size_t)row * 512 + kcol) >> 1] = pack_h2(r0, r1);
                        }
                    } else {                        // V: plain fp16
                        const int vcol = col - 2560;
                        ((uint32_t*)VF)[((size_t)rlo * 512 + vcol) >> 1]       = pack_h2(v0a, v1a);
                        ((uint32_t*)VF)[((size_t)(rlo + 8) * 512 + vcol) >> 1] = pack_h2(v0b, v1b);
                    }
                }
            }
        }
    }
}

// ---------------------------------------------------------------------------
// Flash attention (unchanged from R11): Q/K/V single fp16, register P.
// Block: q-tile 128, 8 warps, j-tiles of 64. SMEM 104448 -> 2 CTAs/SM.
// ---------------------------------------------------------------------------
#define ATT_SMEM 104448

__global__ __launch_bounds__(256, 2)
void attn_mma(const __half* __restrict__ qf,
              const __half* __restrict__ kf, const __half* __restrict__ vf,
              __half* __restrict__ of)
{
    extern __shared__ char smem[];
    const uint32_t sb = smem_to_u32(smem);
    const int tid = threadIdx.x, lane = tid & 31, wq = tid >> 5;
    const int i0 = blockIdx.x * 128;
    const int h  = blockIdx.y, b = blockIdx.z, kvh = h >> 2;

    for (int c = tid; c < 2048; c += 256) {
        int r = c >> 4, ch = c & 15;
        uint32_t dst = sb + r * 272 + ch * 16;
        size_t src = (size_t)(b * Sn + i0 + r) * (NQ * HD) + h * HD + ch * 8;
        cpa16(dst, qf + src);
    }
    CP_COMMIT();

    int jt0 = i0 - WINDOW; if (jt0 < 0) jt0 = 0;
    const int ntiles = (i0 + 64 - jt0) / 64 + 1;

    auto stage_kv = [&](int t, int buf) {
        int jt = jt0 + t * 64;
        uint32_t s0 = sb + 34816 + buf * 34816;
        for (int c = tid; c < 1024; c += 256) {
            int r = c >> 4, ch = c & 15;
            uint32_t dst = s0 + r * 272 + ch * 16;
            size_t src = (size_t)(b * Sn + jt + r) * (NKV * HD) + kvh * HD + ch * 8;
            cpa16(dst,         kf + src);
            cpa16(dst + 17408, vf + src);
        }
        CP_COMMIT();
    };

    stage_kv(0, 0);

    const int g = lane >> 2, t4 = lane & 3;
    const int a_r  = ((lane >> 3) & 1) * 8 + (lane & 7);
    const int a_c8 = (lane >> 4) & 1;
    const int w0 = i0 + wq * 16;

    float m_r[2] = {-1e30f, -1e30f};
    float l_r[2] = {0.f, 0.f};
    float o_acc[16][4];
    #pragma unroll
    for (int nb = 0; nb < 16; ++nb)
        #pragma unroll
        for (int c = 0; c < 4; ++c) o_acc[nb][c] = 0.f;

    for (int t = 0; t < ntiles; ++t) {
        const int buf = t & 1;
        if (t + 1 < ntiles) { stage_kv(t + 1, buf ^ 1); CP_WAIT1(); }
        else                { CP_WAIT0(); }
        __syncthreads();

        const int jt = jt0 + t * 64;
        const bool active = (jt <= w0 + 15) && (jt + 63 >= w0 - WINDOW);

        if (active) {
            const uint32_t sQf = sb;
            const uint32_t sKf = sb + 34816 + buf * 34816;
            const uint32_t sVf = sKf + 17408;

            float s_c[8][4];
            #pragma unroll
            for (int nb = 0; nb < 8; ++nb)
                #pragma unroll
                for (int c = 0; c < 4; ++c) s_c[nb][c] = 0.f;

            #pragma unroll
            for (int ks = 0; ks < 8; ++ks) {
                uint32_t aq[4];
                uint32_t qoff = (uint32_t)((wq * 16 + a_r) * 272 + (ks * 16 + a_c8 * 8) * 2);
                ldsm4(aq, sQf + qoff);
                #pragma unroll
                for (int p = 0; p < 4; ++p) {
                    uint32_t bk[4];
                    uint32_t koff = (uint32_t)((p * 16 + a_r) * 272 + (ks * 16 + a_c8 * 8) * 2);
                    ldsm4(bk, sKf + koff);
                    uint32_t b0[2] = {bk[0], bk[2]}, b1[2] = {bk[1], bk[3]};
                    hmma16(s_c[2*p],   aq, b0);
                    hmma16(s_c[2*p+1], aq, b1);
                }
            }

            const bool need_mask = (jt + 63 > w0) || (w0 + 15 - jt > WINDOW);
            float mt[2] = {-1e30f, -1e30f};
            if (need_mask) {
                #pragma unroll
                for (int nb = 0; nb < 8; ++nb) {
                    const int jbase = jt + nb * 8 + t4 * 2;
                    #pragma unroll
                    for (int c = 0; c < 4; ++c) {
                        const int rr = c >> 1;
                        const int i = w0 + g + rr * 8;
                        const int j = jbase + (c & 1);
                        if (!((j <= i) && (i - j <= WINDOW)))
                            s_c[nb][c] = -1e30f;
                        mt[rr] = fmaxf(mt[rr], s_c[nb][c]);
                    }
                }
            } else {
                #pragma unroll
                for (int nb = 0; nb < 8; ++nb)
                    #pragma unroll
                    for (int c = 0; c < 4; ++c)
                        mt[c >> 1] = fmaxf(mt[c >> 1], s_c[nb][c]);
            }
            float corr[2];
            #pragma unroll
            for (int rr = 0; rr < 2; ++rr) {
                mt[rr] = fmaxf(mt[rr], __shfl_xor_sync(0xffffffffu, mt[rr], 1));
                mt[rr] = fmaxf(mt[rr], __shfl_xor_sync(0xffffffffu, mt[rr], 2));
                float mn = fmaxf(m_r[rr], mt[rr]);
                corr[rr] = exp2f(m_r[rr] - mn);
                m_r[rr] = mn;
            }
            float ps[2] = {0.f, 0.f};
            #pragma unroll
            for (int nb = 0; nb < 8; ++nb) {
                #pragma unroll
                for (int c = 0; c < 4; ++c) {
                    const int rr = c >> 1;
                    float p = exp2f(s_c[nb][c] - m_r[rr]);
                    s_c[nb][c] = p;
                    ps[rr] += p;
                }
            }
            #pragma unroll
            for (int rr = 0; rr < 2; ++rr) {
                ps[rr] += __shfl_xor_sync(0xffffffffu, ps[rr], 1);
                ps[rr] += __shfl_xor_sync(0xffffffffu, ps[rr], 2);
                l_r[rr] = l_r[rr] * corr[rr] + ps[rr];
            }
            #pragma unroll
            for (int nb = 0; nb < 16; ++nb) {
                o_acc[nb][0] *= corr[0]; o_acc[nb][1] *= corr[0];
                o_acc[nb][2] *= corr[1]; o_acc[nb][3] *= corr[1];
            }

            #pragma unroll
            for (int ks = 0; ks < 4; ++ks) {
                uint32_t ap[4];
                ap[0] = pack_h2(s_c[2*ks][0],   s_c[2*ks][1]);
                ap[1] = pack_h2(s_c[2*ks][2],   s_c[2*ks][3]);
                ap[2] = pack_h2(s_c[2*ks+1][0], s_c[2*ks+1][1]);
                ap[3] = pack_h2(s_c[2*ks+1][2], s_c[2*ks+1][3]);
                #pragma unroll
                for (int p2 = 0; p2 < 8; ++p2) {
                    uint32_t bv[4];
                    uint32_t voff = (uint32_t)((ks * 16 + a_r) * 272 + (p2 * 16 + a_c8 * 8) * 2);
                    ldsm4t(bv, sVf + voff);
                    uint32_t b0[2] = {bv[0], bv[1]}, b1[2] = {bv[2], bv[3]};
                    hmma16(o_acc[2*p2],   ap, b0);
                    hmma16(o_acc[2*p2+1], ap, b1);
                }
            }
        }
        __syncthreads();
    }

    const float inv0 = 1.0f / l_r[0], inv1 = 1.0f / l_r[1];
    #pragma unroll
    for (int nb = 0; nb < 16; ++nb) {
        const int d = nb * 8 + t4 * 2;
        #pragma unroll
        for (int rr = 0; rr < 2; ++rr) {
            const int i = w0 + g + rr * 8;
            const float inv = rr ? inv1 : inv0;
            __half2 hv = __floats2half2_rn(o_acc[nb][rr*2] * inv, o_acc[nb][rr*2+1] * inv);
            const size_t o32 = ((size_t)(b * Sn + i) * NQ + h) * 64 + (d >> 1);
            ((uint32_t*)of)[o32] = *(uint32_t*)&hv;
        }
    }
}

// ---------------------------------------------------------------------------
extern "C" void kernel_launch(void* const* d_in, const int* in_sizes, int n_in,
                              void* d_out, int out_size)
{
    const float* x  = (const float*)d_in[0];
    const float* Wq = (const float*)d_in[1];
    const float* bq = (const float*)d_in[2];
    const float* Wk = (const float*)d_in[3];
    const float* bk = (const float*)d_in[4];
    const float* Wv = (const float*)d_in[5];
    const float* bv = (const float*)d_in[6];
    const float* Wo = (const float*)d_in[7];
    const float* bo = (const float*)d_in[8];
    float* out = (float*)d_out;

    __half *xf, *of, *wqkv, *wo, *qf16, *kf16, *vf16;
    float *bqkv; float2 *rope;
    cudaGetSymbolAddress((void**)&xf, g_xf);     cudaGetSymbolAddress((void**)&of, g_of);
    cudaGetSymbolAddress((void**)&wqkv, g_wqkv); cudaGetSymbolAddress((void**)&wo, g_wo);
    cudaGetSymbolAddress((void**)&bqkv, g_bqkv); cudaGetSymbolAddress((void**)&rope, g_rope);
    cudaGetSymbolAddress((void**)&qf16, g_qf16);
    cudaGetSymbolAddress((void**)&kf16, g_kf16); cudaGetSymbolAddress((void**)&vf16, g_vf16);

    cudaFuncSetAttribute(gemm_f16<0>, cudaFuncAttributeMaxDynamicSharedMemorySize, GEMM_SMEM);
    cudaFuncSetAttribute(gemm_f16<1>, cudaFuncAttributeMaxDynamicSharedMemorySize, GEMM_SMEM);
    cudaFuncSetAttribute(attn_mma, cudaFuncAttributeMaxDynamicSharedMemorySize, ATT_SMEM);

    // Converts + rope table + bias concat
    const int n4x = Mrows * En / 4;
    cvt_f16<<<n4x / 1024, 1024>>>((const float4*)x, (uint2*)xf, n4x);
    cvt_w<<<dim3(64, 64, 4), dim3(32, 8)>>>(Wq, Wk, Wv, Wo, wqkv, wo);
    build_tbl<<<512, 256>>>(rope, bq, bk, bv, bqkv);

    // Fused QKV projection (persistent, rope LUT epilogue): 768 tiles / 304 CTAs
    gemm_f16<1><<<304, 256, GEMM_SMEM>>>(xf, wqkv, bqkv, nullptr,
                                         qf16, kf16, vf16, rope,
                                         Mrows, 3072, En);

    // Flash attention (fp16, register P), fp16 output
    attn_mma<<<dim3(Sn/128, NQ, Bn), 256, ATT_SMEM>>>(qf16, kf16, vf16, of);

    // Output projection (persistent, fp32 out): 512 tiles / 304 CTAs
    gemm_f16<0><<<304, 256, GEMM_SMEM>>>(of, wo, bo, out,
                                         nullptr, nullptr, nullptr, nullptr,
                                         Mrows, 2048, En);
}

// round 13
// speedup vs baseline: 1.0857x; 1.0857x over previous
#include <cuda_runtime.h>
#include <cuda_fp16.h>
#include <math.h>
#include <cstdint>

// Problem constants
#define Bn 2
#define Sn 2048
#define En 2048
#define NQ 16
#define NKV 4
#define HD 128
#define WINDOW 512
#define Mrows (Bn*Sn)          // 4096

// ---------------------------------------------------------------------------
// Scratch (device globals; no allocation allowed)
// ---------------------------------------------------------------------------
__device__ __half g_xf[(size_t)Mrows * En];        // x fp16
__device__ __half g_of[(size_t)Mrows * En];        // attention out fp16
__device__ __half g_wqkv[(size_t)3072 * 2048];     // [Wq|Wk|Wv] transposed [N,K]
__device__ __half g_wo[(size_t)2048 * 2048];
__device__ float  g_bqkv[3072];                    // [bq|bk|bv]
__device__ float2 g_rope[(size_t)Sn * 64];         // (cos,sin) per (pos,d)
// attention operands (written directly by GEMM epilogues)
__device__ __half g_qf16[(size_t)Mrows * NQ * HD]; // rope'd, scaled
__device__ __half g_kf16[(size_t)Mrows * NKV * HD];// rope'd
__device__ __half g_vf16[(size_t)Mrows * NKV * HD];

// ---------------------------------------------------------------------------
// PTX helpers
// ---------------------------------------------------------------------------
__device__ __forceinline__ uint32_t smem_to_u32(const void* p) {
    uint32_t a;
    asm("{ .reg .u64 t; cvta.to.shared.u64 t, %1; cvt.u32.u64 %0, t; }" : "=r"(a) : "l"(p));
    return a;
}
__device__ __forceinline__ void ldsm4(uint32_t* r, uint32_t addr) {
    asm volatile("ldmatrix.sync.aligned.m8n8.x4.shared.b16 {%0,%1,%2,%3}, [%4];"
        : "=r"(r[0]), "=r"(r[1]), "=r"(r[2]), "=r"(r[3]) : "r"(addr));
}
__device__ __forceinline__ void ldsm4t(uint32_t* r, uint32_t addr) {
    asm volatile("ldmatrix.sync.aligned.m8n8.x4.trans.shared.b16 {%0,%1,%2,%3}, [%4];"
        : "=r"(r[0]), "=r"(r[1]), "=r"(r[2]), "=r"(r[3]) : "r"(addr));
}
__device__ __forceinline__ void hmma16(float* c, const uint32_t* a, const uint32_t* b) {
    asm volatile("mma.sync.aligned.m16n8k16.row.col.f32.f16.f16.f32 "
        "{%0,%1,%2,%3}, {%4,%5,%6,%7}, {%8,%9}, {%0,%1,%2,%3};"
        : "+f"(c[0]), "+f"(c[1]), "+f"(c[2]), "+f"(c[3])
        : "r"(a[0]), "r"(a[1]), "r"(a[2]), "r"(a[3]), "r"(b[0]), "r"(b[1]));
}
__device__ __forceinline__ void cpa16(uint32_t dst, const void* src) {
    asm volatile("cp.async.cg.shared.global [%0], [%1], 16;" :: "r"(dst), "l"(src));
}
#define CP_COMMIT() asm volatile("cp.async.commit_group;" ::: "memory")
#define CP_WAIT0()  asm volatile("cp.async.wait_group 0;" ::: "memory")
#define CP_WAIT1()  asm volatile("cp.async.wait_group 1;" ::: "memory")

__device__ __forceinline__ uint32_t pack_h2(float a, float b) {
    __half2 v = __floats2half2_rn(a, b);
    return *(uint32_t*)&v;
}

// q scale: (1/sqrt(128)) * log2(e)  — softmax done in exp2 space
#define QSCALE 0.1275174056563446f
#define LOG2_10000 13.287712379549449f

// ---------------------------------------------------------------------------
// fp32 -> fp16, 4 elems/thread.
// ---------------------------------------------------------------------------
__global__ void cvt_f16(const float4* __restrict__ in, uint2* __restrict__ out, int n4)
{
    int i = blockIdx.x * blockDim.x + threadIdx.x;
    if (i >= n4) return;
    float4 v = in[i];
    __half2 a = __floats2half2_rn(v.x, v.y);
    __half2 b = __floats2half2_rn(v.z, v.w);
    uint2 o; o.x = *(uint32_t*)&a; o.y = *(uint32_t*)&b;
    out[i] = o;
}

// ---------------------------------------------------------------------------
// All weight transposes in one kernel. z selects the weight.
// ---------------------------------------------------------------------------
__global__ void cvt_w(const float* __restrict__ Wq, const float* __restrict__ Wk,
                      const float* __restrict__ Wv, const float* __restrict__ Wo,
                      __half* __restrict__ wqkv, __half* __restrict__ wo)
{
    const int z = blockIdx.z;
    const float* src; __half* dst; int N;
    if (z == 0)      { src = Wq; dst = wqkv;                       N = 2048; }
    else if (z == 1) { src = Wk; dst = wqkv + (size_t)2048 * 2048; N = 512; }
    else if (z == 2) { src = Wv; dst = wqkv + (size_t)2560 * 2048; N = 512; }
    else             { src = Wo; dst = wo;                          N = 2048; }
    const int n0 = blockIdx.x * 32;
    if (n0 >= N) return;
    const int k0 = blockIdx.y * 32;   // K = 2048 always
    __shared__ float t[32][33];
    const int tx = threadIdx.x, ty = threadIdx.y;
    #pragma unroll
    for (int j = ty; j < 32; j += 8)
        t[j][tx] = src[(size_t)(k0 + j) * N + n0 + tx];
    __syncthreads();
    #pragma unroll
    for (int j = ty; j < 32; j += 8)
        dst[(size_t)(n0 + j) * 2048 + k0 + tx] = __float2half(t[tx][j]);
}

// ---------------------------------------------------------------------------
// Build rope table (cos,sin) for (pos, d) and concat biases.
// ---------------------------------------------------------------------------
__global__ void build_tbl(float2* __restrict__ tbl,
                          const float* __restrict__ bq, const float* __restrict__ bk,
                          const float* __restrict__ bv, float* __restrict__ bqkv)
{
    int i = blockIdx.x * 256 + threadIdx.x;     // 131072 threads
    int d = i & 63, pos = i >> 6;
    float freq = exp2f(-((float)(2 * d) / 128.0f) * LOG2_10000);
    float ang = (float)pos * freq;
    tbl[i] = make_float2(cosf(ang), sinf(ang));
    if (i < 3072) {
        float b;
        if (i < 2048) b = bq[i];
        else if (i < 2560) b = bk[i - 2048];
        else b = bv[i - 2560];
        bqkv[i] = b;
    }
}

// ---------------------------------------------------------------------------
// fp16 HMMA GEMM (R11 structure, single-barrier inner loop):
// BM=128 BN=128 BK=64, 256 thr, 2-stage cp.async, 2 CTAs/SM.
// Loop: WAIT0 -> sync -> issue(it+1) -> compute(it).   (one barrier/iter)
//   MODE 0: C fp32 = A@B^T + bias                       (output projection)
//   MODE 1: fused QKV epilogue (rope LUT; regions CTA-uniform by col)
// ---------------------------------------------------------------------------
#define STG 32768
#define GEMM_SMEM (2*STG)

template<int MODE>
__global__ __launch_bounds__(256, 2)
void gemm_f16(const __half* __restrict__ A, const __half* __restrict__ B,
              const float* __restrict__ bias, float* __restrict__ C,
              __half* __restrict__ QF, __half* __restrict__ KF, __half* __restrict__ VF,
              const float2* __restrict__ rope,
              int M, int N, int K)
{
    extern __shared__ char smem[];
    const uint32_t sb = smem_to_u32(smem);
    const int tid = threadIdx.x;
    const int wid = tid >> 5;
    const int lane = tid & 31;
    const int wm = wid >> 1;
    const int wn = wid & 1;
    const int row0 = blockIdx.y * 128;
    const int col0 = blockIdx.x * 128;

    const int ld_row = tid >> 3;
    const int ld_seg = tid & 7;

    float acc[2][8][4];
    #pragma unroll
    for (int a = 0; a < 2; ++a)
        #pragma unroll
        for (int b = 0; b < 8; ++b)
            #pragma unroll
            for (int c = 0; c < 4; ++c) acc[a][b][c] = 0.f;

    const int iters = K >> 6;

    auto issue = [&](int it, int stage) {
        const size_t kk = (size_t)(it << 6) + (ld_seg << 3);
        const uint32_t s0 = sb + stage * STG;
        #pragma unroll
        for (int j = 0; j < 4; ++j) {
            const int row = ld_row + j * 32;
            uint32_t bo = (uint32_t)(row * 128 + ld_seg * 16);
            uint32_t sw = bo ^ ((bo >> 3) & 0x70);
            cpa16(s0 + sw,         A + (size_t)(row0 + row) * K + kk);
            cpa16(s0 + 16384 + sw, B + (size_t)(col0 + row) * K + kk);
        }
        CP_COMMIT();
    };

    issue(0, 0);

    const int sub = lane >> 3;
    const int rr  = lane & 7;
    const int arow[2] = { wm*32 + 0*16 + (sub & 1)*8 + rr,
                          wm*32 + 1*16 + (sub & 1)*8 + rr };
    const int acol = (sub >> 1) * 16;
    const int brow[4] = { wn*64 + 0*16 + (sub >> 1)*8 + rr,
                          wn*64 + 1*16 + (sub >> 1)*8 + rr,
                          wn*64 + 2*16 + (sub >> 1)*8 + rr,
                          wn*64 + 3*16 + (sub >> 1)*8 + rr };
    const int bcol = (sub & 1) * 16;

    for (int it = 0; it < iters; ++it) {
        const int stage = it & 1;
        // Data for iteration `it` was issued last iteration (or prologue).
        CP_WAIT0();
        __syncthreads();           // publish loads; also fences WAR for issue below
        if (it + 1 < iters) issue(it + 1, stage ^ 1);

        const uint32_t sA = sb + stage * STG;
        const uint32_t sB = sA + 16384;

        #pragma unroll
        for (int ks = 0; ks < 4; ++ks) {
            uint32_t af[2][4], bf[4][4];
            #pragma unroll
            for (int mi = 0; mi < 2; ++mi) {
                uint32_t off = (uint32_t)(arow[mi] * 128 +
                               ((ks*32 + acol) ^ ((arow[mi] & 7) << 4)));
                ldsm4(af[mi], sA + off);
            }
            #pragma unroll
            for (int p = 0; p < 4; ++p) {
                uint32_t off = (uint32_t)(brow[p] * 128 +
                               ((ks*32 + bcol) ^ ((brow[p] & 7) << 4)));
                ldsm4(bf[p], sB + off);
            }
            #pragma unroll
            for (int mi = 0; mi < 2; ++mi)
                #pragma unroll
                for (int ni = 0; ni < 8; ++ni)
                    hmma16(acc[mi][ni], af[mi], &bf[ni >> 1][(ni & 1) * 2]);
        }
    }

    const int g = lane >> 2, t4 = lane & 3;
    #pragma unroll
    for (int mi = 0; mi < 2; ++mi) {
        const int rlo = row0 + wm*32 + mi*16 + g;
        #pragma unroll
        for (int ni = 0; ni < 8; ++ni) {
            const int col = col0 + wn*64 + ni*8 + 2*t4;   // even
            const float b0 = bias[col], b1 = bias[col + 1];
            float v0a = acc[mi][ni][0] + b0, v1a = acc[mi][ni][1] + b1; // row rlo
            float v0b = acc[mi][ni][2] + b0, v1b = acc[mi][ni][3] + b1; // row rlo+8

            if (MODE == 0) {
                *(float2*)(C + (size_t)rlo * N + col)       = make_float2(v0a, v1a);
                *(float2*)(C + (size_t)(rlo + 8) * N + col) = make_float2(v0b, v1b);
            } else {
                if (col < 2048) {               // Q: rope + scale -> fp16
                    const int d = (col & 127) >> 1;
                    #pragma unroll
                    for (int rsel = 0; rsel < 2; ++rsel) {
                        const int row = rlo + rsel * 8;
                        const float2 cs = rope[(size_t)(row & (Sn-1)) * 64 + d];
                        float e = rsel ? v0b : v0a, o = rsel ? v1b : v1a;
                        float r0 = (e * cs.x - o * cs.y) * QSCALE;
                        float r1 = (e * cs.y + o * cs.x) * QSCALE;
                        ((uint32_t*)QF)[((size_t)row * 2048 + col) >> 1] = pack_h2(r0, r1);
                    }
                } else if (col < 2560) {        // K: rope -> fp16
                    const int kcol = col - 2048;
                    const int d = (kcol & 127) >> 1;
                    #pragma unroll
                    for (int rsel = 0; rsel < 2; ++rsel) {
                        const int row = rlo + rsel * 8;
                        const float2 cs = rope[(size_t)(row & (Sn-1)) * 64 + d];
                        float e = rsel ? v0b : v0a, o = rsel ? v1b : v1a;
                        float r0 = e * cs.x - o * cs.y;
                        float r1 = e * cs.y + o * cs.x;
                        ((uint32_t*)KF)[((size_t)row * 512 + kcol) >> 1] = pack_h2(r0, r1);
                    }
                } else {                        // V: plain fp16
                    const int vcol = col - 2560;
                    ((uint32_t*)VF)[((size_t)rlo * 512 + vcol) >> 1]       = pack_h2(v0a, v1a);
                    ((uint32_t*)VF)[((size_t)(rlo + 8) * 512 + vcol) >> 1] = pack_h2(v0b, v1b);
                }
            }
        }
    }
}

// ---------------------------------------------------------------------------
// Flash attention (unchanged from R11): Q/K/V single fp16, register P.
// Block: q-tile 128, 8 warps, j-tiles of 64. SMEM 104448 -> 2 CTAs/SM.
// ---------------------------------------------------------------------------
#define ATT_SMEM 104448

__global__ __launch_bounds__(256, 2)
void attn_mma(const __half* __restrict__ qf,
              const __half* __restrict__ kf, const __half* __restrict__ vf,
              __half* __restrict__ of)
{
    extern __shared__ char smem[];
    const uint32_t sb = smem_to_u32(smem);
    const int tid = threadIdx.x, lane = tid & 31, wq = tid >> 5;
    const int i0 = blockIdx.x * 128;
    const int h  = blockIdx.y, b = blockIdx.z, kvh = h >> 2;

    for (int c = tid; c < 2048; c += 256) {
        int r = c >> 4, ch = c & 15;
        uint32_t dst = sb + r * 272 + ch * 16;
        size_t src = (size_t)(b * Sn + i0 + r) * (NQ * HD) + h * HD + ch * 8;
        cpa16(dst, qf + src);
    }
    CP_COMMIT();

    int jt0 = i0 - WINDOW; if (jt0 < 0) jt0 = 0;
    const int ntiles = (i0 + 64 - jt0) / 64 + 1;

    auto stage_kv = [&](int t, int buf) {
        int jt = jt0 + t * 64;
        uint32_t s0 = sb + 34816 + buf * 34816;
        for (int c = tid; c < 1024; c += 256) {
            int r = c >> 4, ch = c & 15;
            uint32_t dst = s0 + r * 272 + ch * 16;
            size_t src = (size_t)(b * Sn + jt + r) * (NKV * HD) + kvh * HD + ch * 8;
            cpa16(dst,         kf + src);
            cpa16(dst + 17408, vf + src);
        }
        CP_COMMIT();
    };

    stage_kv(0, 0);

    const int g = lane >> 2, t4 = lane & 3;
    const int a_r  = ((lane >> 3) & 1) * 8 + (lane & 7);
    const int a_c8 = (lane >> 4) & 1;
    const int w0 = i0 + wq * 16;

    float m_r[2] = {-1e30f, -1e30f};
    float l_r[2] = {0.f, 0.f};
    float o_acc[16][4];
    #pragma unroll
    for (int nb = 0; nb < 16; ++nb)
        #pragma unroll
        for (int c = 0; c < 4; ++c) o_acc[nb][c] = 0.f;

    for (int t = 0; t < ntiles; ++t) {
        const int buf = t & 1;
        if (t + 1 < ntiles) { stage_kv(t + 1, buf ^ 1); CP_WAIT1(); }
        else                { CP_WAIT0(); }
        __syncthreads();

        const int jt = jt0 + t * 64;
        const bool active = (jt <= w0 + 15) && (jt + 63 >= w0 - WINDOW);

        if (active) {
            const uint32_t sQf = sb;
            const uint32_t sKf = sb + 34816 + buf * 34816;
            const uint32_t sVf = sKf + 17408;

            float s_c[8][4];
            #pragma unroll
            for (int nb = 0; nb < 8; ++nb)
                #pragma unroll
                for (int c = 0; c < 4; ++c) s_c[nb][c] = 0.f;

            #pragma unroll
            for (int ks = 0; ks < 8; ++ks) {
                uint32_t aq[4];
                uint32_t qoff = (uint32_t)((wq * 16 + a_r) * 272 + (ks * 16 + a_c8 * 8) * 2);
                ldsm4(aq, sQf + qoff);
                #pragma unroll
                for (int p = 0; p < 4; ++p) {
                    uint32_t bk[4];
                    uint32_t koff = (uint32_t)((p * 16 + a_r) * 272 + (ks * 16 + a_c8 * 8) * 2);
                    ldsm4(bk, sKf + koff);
                    uint32_t b0[2] = {bk[0], bk[2]}, b1[2] = {bk[1], bk[3]};
                    hmma16(s_c[2*p],   aq, b0);
                    hmma16(s_c[2*p+1], aq, b1);
                }
            }

            const bool need_mask = (jt + 63 > w0) || (w0 + 15 - jt > WINDOW);
            float mt[2] = {-1e30f, -1e30f};
            if (need_mask) {
                #pragma unroll
                for (int nb = 0; nb < 8; ++nb) {
                    const int jbase = jt + nb * 8 + t4 * 2;
                    #pragma unroll
                    for (int c = 0; c < 4; ++c) {
                        const int rr = c >> 1;
                        const int i = w0 + g + rr * 8;
                        const int j = jbase + (c & 1);
                        if (!((j <= i) && (i - j <= WINDOW)))
                            s_c[nb][c] = -1e30f;
                        mt[rr] = fmaxf(mt[rr], s_c[nb][c]);
                    }
                }
            } else {
                #pragma unroll
                for (int nb = 0; nb < 8; ++nb)
                    #pragma unroll
                    for (int c = 0; c < 4; ++c)
                        mt[c >> 1] = fmaxf(mt[c >> 1], s_c[nb][c]);
            }
            float corr[2];
            #pragma unroll
            for (int rr = 0; rr < 2; ++rr) {
                mt[rr] = fmaxf(mt[rr], __shfl_xor_sync(0xffffffffu, mt[rr], 1));
                mt[rr] = fmaxf(mt[rr], __shfl_xor_sync(0xffffffffu, mt[rr], 2));
                float mn = fmaxf(m_r[rr], mt[rr]);
                corr[rr] = exp2f(m_r[rr] - mn);
                m_r[rr] = mn;
            }
            float ps[2] = {0.f, 0.f};
            #pragma unroll
            for (int nb = 0; nb < 8; ++nb) {
                #pragma unroll
                for (int c = 0; c < 4; ++c) {
                    const int rr = c >> 1;
                    float p = exp2f(s_c[nb][c] - m_r[rr]);
                    s_c[nb][c] = p;
                    ps[rr] += p;
                }
            }
            #pragma unroll
            for (int rr = 0; rr < 2; ++rr) {
                ps[rr] += __shfl_xor_sync(0xffffffffu, ps[rr], 1);
                ps[rr] += __shfl_xor_sync(0xffffffffu, ps[rr], 2);
                l_r[rr] = l_r[rr] * corr[rr] + ps[rr];
            }
            #pragma unroll
            for (int nb = 0; nb < 16; ++nb) {
                o_acc[nb][0] *= corr[0]; o_acc[nb][1] *= corr[0];
                o_acc[nb][2] *= corr[1]; o_acc[nb][3] *= corr[1];
            }

            #pragma unroll
            for (int ks = 0; ks < 4; ++ks) {
                uint32_t ap[4];
                ap[0] = pack_h2(s_c[2*ks][0],   s_c[2*ks][1]);
                ap[1] = pack_h2(s_c[2*ks][2],   s_c[2*ks][3]);
                ap[2] = pack_h2(s_c[2*ks+1][0], s_c[2*ks+1][1]);
                ap[3] = pack_h2(s_c[2*ks+1][2], s_c[2*ks+1][3]);
                #pragma unroll
                for (int p2 = 0; p2 < 8; ++p2) {
                    uint32_t bv[4];
                    uint32_t voff = (uint32_t)((ks * 16 + a_r) * 272 + (p2 * 16 + a_c8 * 8) * 2);
                    ldsm4t(bv, sVf + voff);
                    uint32_t b0[2] = {bv[0], bv[1]}, b1[2] = {bv[2], bv[3]};
                    hmma16(o_acc[2*p2],   ap, b0);
                    hmma16(o_acc[2*p2+1], ap, b1);
                }
            }
        }
        __syncthreads();
    }

    const float inv0 = 1.0f / l_r[0], inv1 = 1.0f / l_r[1];
    #pragma unroll
    for (int nb = 0; nb < 16; ++nb) {
        const int d = nb * 8 + t4 * 2;
        #pragma unroll
        for (int rr = 0; rr < 2; ++rr) {
            const int i = w0 + g + rr * 8;
            const float inv = rr ? inv1 : inv0;
            __half2 hv = __floats2half2_rn(o_acc[nb][rr*2] * inv, o_acc[nb][rr*2+1] * inv);
            const size_t o32 = ((size_t)(b * Sn + i) * NQ + h) * 64 + (d >> 1);
            ((uint32_t*)of)[o32] = *(uint32_t*)&hv;
        }
    }
}

// ---------------------------------------------------------------------------
extern "C" void kernel_launch(void* const* d_in, const int* in_sizes, int n_in,
                              void* d_out, int out_size)
{
    const float* x  = (const float*)d_in[0];
    const float* Wq = (const float*)d_in[1];
    const float* bq = (const float*)d_in[2];
    const float* Wk = (const float*)d_in[3];
    const float* bk = (const float*)d_in[4];
    const float* Wv = (const float*)d_in[5];
    const float* bv = (const float*)d_in[6];
    const float* Wo = (const float*)d_in[7];
    const float* bo = (const float*)d_in[8];
    float* out = (float*)d_out;

    __half *xf, *of, *wqkv, *wo, *qf16, *kf16, *vf16;
    float *bqkv; float2 *rope;
    cudaGetSymbolAddress((void**)&xf, g_xf);     cudaGetSymbolAddress((void**)&of, g_of);
    cudaGetSymbolAddress((void**)&wqkv, g_wqkv); cudaGetSymbolAddress((void**)&wo, g_wo);
    cudaGetSymbolAddress((void**)&bqkv, g_bqkv); cudaGetSymbolAddress((void**)&rope, g_rope);
    cudaGetSymbolAddress((void**)&qf16, g_qf16);
    cudaGetSymbolAddress((void**)&kf16, g_kf16); cudaGetSymbolAddress((void**)&vf16, g_vf16);

    cudaFuncSetAttribute(gemm_f16<0>, cudaFuncAttributeMaxDynamicSharedMemorySize, GEMM_SMEM);
    cudaFuncSetAttribute(gemm_f16<1>, cudaFuncAttributeMaxDynamicSharedMemorySize, GEMM_SMEM);
    cudaFuncSetAttribute(attn_mma, cudaFuncAttributeMaxDynamicSharedMemorySize, ATT_SMEM);

    // Converts + rope table + bias concat
    const int n4x = Mrows * En / 4;
    cvt_f16<<<n4x / 1024, 1024>>>((const float4*)x, (uint2*)xf, n4x);
    cvt_w<<<dim3(64, 64, 4), dim3(32, 8)>>>(Wq, Wk, Wv, Wo, wqkv, wo);
    build_tbl<<<512, 256>>>(rope, bq, bk, bv, bqkv);

    // Fused QKV projection (rope LUT epilogue)
    gemm_f16<1><<<dim3(24, 32), 256, GEMM_SMEM>>>(xf, wqkv, bqkv, nullptr,
                                                  qf16, kf16, vf16, rope,
                                                  Mrows, 3072, En);

    // Flash attention (fp16, register P), fp16 output
    attn_mma<<<dim3(Sn/128, NQ, Bn), 256, ATT_SMEM>>>(qf16, kf16, vf16, of);

    // Output projection (fp32 out)
    gemm_f16<0><<<dim3(16, 32), 256, GEMM_SMEM>>>(of, wo, bo, out,
                                                  nullptr, nullptr, nullptr, nullptr,
                                                  Mrows, 2048, En);
}

// round 14
// speedup vs baseline: 1.0889x; 1.0029x over previous
#include <cuda_runtime.h>
#include <cuda_fp16.h>
#include <math.h>
#include <cstdint>

// Problem constants
#define Bn 2
#define Sn 2048
#define En 2048
#define NQ 16
#define NKV 4
#define HD 128
#define WINDOW 512
#define Mrows (Bn*Sn)          // 4096

// ---------------------------------------------------------------------------
// Scratch (device globals; no allocation allowed)
// ---------------------------------------------------------------------------
__device__ __half g_xf[(size_t)Mrows * En];        // x fp16
__device__ __half g_of[(size_t)Mrows * En];        // attention out fp16
__device__ __half g_wqkv[(size_t)3072 * 2048];     // [Wq|Wk|Wv] transposed [N,K]
__device__ __half g_wo[(size_t)2048 * 2048];
__device__ float  g_bqkv[3072];                    // [bq|bk|bv]
__device__ float2 g_rope[(size_t)Sn * 64];         // (cos,sin) per (pos,d)
// attention operands (written directly by GEMM epilogues)
__device__ __half g_qf16[(size_t)Mrows * NQ * HD]; // rope'd, scaled
__device__ __half g_kf16[(size_t)Mrows * NKV * HD];// rope'd
__device__ __half g_vf16[(size_t)Mrows * NKV * HD];

// ---------------------------------------------------------------------------
// PTX helpers
// ---------------------------------------------------------------------------
__device__ __forceinline__ uint32_t smem_to_u32(const void* p) {
    uint32_t a;
    asm("{ .reg .u64 t; cvta.to.shared.u64 t, %1; cvt.u32.u64 %0, t; }" : "=r"(a) : "l"(p));
    return a;
}
__device__ __forceinline__ void ldsm4(uint32_t* r, uint32_t addr) {
    asm volatile("ldmatrix.sync.aligned.m8n8.x4.shared.b16 {%0,%1,%2,%3}, [%4];"
        : "=r"(r[0]), "=r"(r[1]), "=r"(r[2]), "=r"(r[3]) : "r"(addr));
}
__device__ __forceinline__ void ldsm4t(uint32_t* r, uint32_t addr) {
    asm volatile("ldmatrix.sync.aligned.m8n8.x4.trans.shared.b16 {%0,%1,%2,%3}, [%4];"
        : "=r"(r[0]), "=r"(r[1]), "=r"(r[2]), "=r"(r[3]) : "r"(addr));
}
__device__ __forceinline__ void hmma16(float* c, const uint32_t* a, const uint32_t* b) {
    asm volatile("mma.sync.aligned.m16n8k16.row.col.f32.f16.f16.f32 "
        "{%0,%1,%2,%3}, {%4,%5,%6,%7}, {%8,%9}, {%0,%1,%2,%3};"
        : "+f"(c[0]), "+f"(c[1]), "+f"(c[2]), "+f"(c[3])
        : "r"(a[0]), "r"(a[1]), "r"(a[2]), "r"(a[3]), "r"(b[0]), "r"(b[1]));
}
__device__ __forceinline__ void cpa16(uint32_t dst, const void* src) {
    asm volatile("cp.async.cg.shared.global [%0], [%1], 16;" :: "r"(dst), "l"(src));
}
#define CP_COMMIT() asm volatile("cp.async.commit_group;" ::: "memory")
#define CP_WAIT0()  asm volatile("cp.async.wait_group 0;" ::: "memory")
#define CP_WAIT1()  asm volatile("cp.async.wait_group 1;" ::: "memory")

__device__ __forceinline__ uint32_t pack_h2(float a, float b) {
    __half2 v = __floats2half2_rn(a, b);
    return *(uint32_t*)&v;
}

// q scale: (1/sqrt(128)) * log2(e)  — softmax done in exp2 space
#define QSCALE 0.1275174056563446f
#define LOG2_10000 13.287712379549449f

// ---------------------------------------------------------------------------
// fp32 -> fp16, 4 elems/thread.
// ---------------------------------------------------------------------------
__global__ void cvt_f16(const float4* __restrict__ in, uint2* __restrict__ out, int n4)
{
    int i = blockIdx.x * blockDim.x + threadIdx.x;
    if (i >= n4) return;
    float4 v = in[i];
    __half2 a = __floats2half2_rn(v.x, v.y);
    __half2 b = __floats2half2_rn(v.z, v.w);
    uint2 o; o.x = *(uint32_t*)&a; o.y = *(uint32_t*)&b;
    out[i] = o;
}

// ---------------------------------------------------------------------------
// All weight transposes in one kernel. z selects the weight.
// ---------------------------------------------------------------------------
__global__ void cvt_w(const float* __restrict__ Wq, const float* __restrict__ Wk,
                      const float* __restrict__ Wv, const float* __restrict__ Wo,
                      __half* __restrict__ wqkv, __half* __restrict__ wo)
{
    const int z = blockIdx.z;
    const float* src; __half* dst; int N;
    if (z == 0)      { src = Wq; dst = wqkv;                       N = 2048; }
    else if (z == 1) { src = Wk; dst = wqkv + (size_t)2048 * 2048; N = 512; }
    else if (z == 2) { src = Wv; dst = wqkv + (size_t)2560 * 2048; N = 512; }
    else             { src = Wo; dst = wo;                          N = 2048; }
    const int n0 = blockIdx.x * 32;
    if (n0 >= N) return;
    const int k0 = blockIdx.y * 32;   // K = 2048 always
    __shared__ float t[32][33];
    const int tx = threadIdx.x, ty = threadIdx.y;
    #pragma unroll
    for (int j = ty; j < 32; j += 8)
        t[j][tx] = src[(size_t)(k0 + j) * N + n0 + tx];
    __syncthreads();
    #pragma unroll
    for (int j = ty; j < 32; j += 8)
        dst[(size_t)(n0 + j) * 2048 + k0 + tx] = __float2half(t[tx][j]);
}

// ---------------------------------------------------------------------------
// Build rope table (cos,sin) for (pos, d) and concat biases.
// ---------------------------------------------------------------------------
__global__ void build_tbl(float2* __restrict__ tbl,
                          const float* __restrict__ bq, const float* __restrict__ bk,
                          const float* __restrict__ bv, float* __restrict__ bqkv)
{
    int i = blockIdx.x * 256 + threadIdx.x;     // 131072 threads
    int d = i & 63, pos = i >> 6;
    float freq = exp2f(-((float)(2 * d) / 128.0f) * LOG2_10000);
    float ang = (float)pos * freq;
    tbl[i] = make_float2(cosf(ang), sinf(ang));
    if (i < 3072) {
        float b;
        if (i < 2048) b = bq[i];
        else if (i < 2560) b = bk[i - 2048];
        else b = bv[i - 2560];
        bqkv[i] = b;
    }
}

// ---------------------------------------------------------------------------
// fp16 HMMA GEMM (R13, unchanged): BM=128 BN=128 BK=64, 256 thr,
// 2-stage cp.async, single-barrier loop, 2 CTAs/SM.
//   MODE 0: C fp32 = A@B^T + bias                       (output projection)
//   MODE 1: fused QKV epilogue (rope LUT; regions CTA-uniform by col)
// ---------------------------------------------------------------------------
#define STG 32768
#define GEMM_SMEM (2*STG)

template<int MODE>
__global__ __launch_bounds__(256, 2)
void gemm_f16(const __half* __restrict__ A, const __half* __restrict__ B,
              const float* __restrict__ bias, float* __restrict__ C,
              __half* __restrict__ QF, __half* __restrict__ KF, __half* __restrict__ VF,
              const float2* __restrict__ rope,
              int M, int N, int K)
{
    extern __shared__ char smem[];
    const uint32_t sb = smem_to_u32(smem);
    const int tid = threadIdx.x;
    const int wid = tid >> 5;
    const int lane = tid & 31;
    const int wm = wid >> 1;
    const int wn = wid & 1;
    const int row0 = blockIdx.y * 128;
    const int col0 = blockIdx.x * 128;

    const int ld_row = tid >> 3;
    const int ld_seg = tid & 7;

    float acc[2][8][4];
    #pragma unroll
    for (int a = 0; a < 2; ++a)
        #pragma unroll
        for (int b = 0; b < 8; ++b)
            #pragma unroll
            for (int c = 0; c < 4; ++c) acc[a][b][c] = 0.f;

    const int iters = K >> 6;

    auto issue = [&](int it, int stage) {
        const size_t kk = (size_t)(it << 6) + (ld_seg << 3);
        const uint32_t s0 = sb + stage * STG;
        #pragma unroll
        for (int j = 0; j < 4; ++j) {
            const int row = ld_row + j * 32;
            uint32_t bo = (uint32_t)(row * 128 + ld_seg * 16);
            uint32_t sw = bo ^ ((bo >> 3) & 0x70);
            cpa16(s0 + sw,         A + (size_t)(row0 + row) * K + kk);
            cpa16(s0 + 16384 + sw, B + (size_t)(col0 + row) * K + kk);
        }
        CP_COMMIT();
    };

    issue(0, 0);

    const int sub = lane >> 3;
    const int rr  = lane & 7;
    const int arow[2] = { wm*32 + 0*16 + (sub & 1)*8 + rr,
                          wm*32 + 1*16 + (sub & 1)*8 + rr };
    const int acol = (sub >> 1) * 16;
    const int brow[4] = { wn*64 + 0*16 + (sub >> 1)*8 + rr,
                          wn*64 + 1*16 + (sub >> 1)*8 + rr,
                          wn*64 + 2*16 + (sub >> 1)*8 + rr,
                          wn*64 + 3*16 + (sub >> 1)*8 + rr };
    const int bcol = (sub & 1) * 16;

    for (int it = 0; it < iters; ++it) {
        const int stage = it & 1;
        CP_WAIT0();
        __syncthreads();           // publish loads; also fences WAR for issue below
        if (it + 1 < iters) issue(it + 1, stage ^ 1);

        const uint32_t sA = sb + stage * STG;
        const uint32_t sB = sA + 16384;

        #pragma unroll
        for (int ks = 0; ks < 4; ++ks) {
            uint32_t af[2][4], bf[4][4];
            #pragma unroll
            for (int mi = 0; mi < 2; ++mi) {
                uint32_t off = (uint32_t)(arow[mi] * 128 +
                               ((ks*32 + acol) ^ ((arow[mi] & 7) << 4)));
                ldsm4(af[mi], sA + off);
            }
            #pragma unroll
            for (int p = 0; p < 4; ++p) {
                uint32_t off = (uint32_t)(brow[p] * 128 +
                               ((ks*32 + bcol) ^ ((brow[p] & 7) << 4)));
                ldsm4(bf[p], sB + off);
            }
            #pragma unroll
            for (int mi = 0; mi < 2; ++mi)
                #pragma unroll
                for (int ni = 0; ni < 8; ++ni)
                    hmma16(acc[mi][ni], af[mi], &bf[ni >> 1][(ni & 1) * 2]);
        }
    }

    const int g = lane >> 2, t4 = lane & 3;
    #pragma unroll
    for (int mi = 0; mi < 2; ++mi) {
        const int rlo = row0 + wm*32 + mi*16 + g;
        #pragma unroll
        for (int ni = 0; ni < 8; ++ni) {
            const int col = col0 + wn*64 + ni*8 + 2*t4;   // even
            const float b0 = bias[col], b1 = bias[col + 1];
            float v0a = acc[mi][ni][0] + b0, v1a = acc[mi][ni][1] + b1; // row rlo
            float v0b = acc[mi][ni][2] + b0, v1b = acc[mi][ni][3] + b1; // row rlo+8

            if (MODE == 0) {
                *(float2*)(C + (size_t)rlo * N + col)       = make_float2(v0a, v1a);
                *(float2*)(C + (size_t)(rlo + 8) * N + col) = make_float2(v0b, v1b);
            } else {
                if (col < 2048) {               // Q: rope + scale -> fp16
                    const int d = (col & 127) >> 1;
                    #pragma unroll
                    for (int rsel = 0; rsel < 2; ++rsel) {
                        const int row = rlo + rsel * 8;
                        const float2 cs = rope[(size_t)(row & (Sn-1)) * 64 + d];
                        float e = rsel ? v0b : v0a, o = rsel ? v1b : v1a;
                        float r0 = (e * cs.x - o * cs.y) * QSCALE;
                        float r1 = (e * cs.y + o * cs.x) * QSCALE;
                        ((uint32_t*)QF)[((size_t)row * 2048 + col) >> 1] = pack_h2(r0, r1);
                    }
                } else if (col < 2560) {        // K: rope -> fp16
                    const int kcol = col - 2048;
                    const int d = (kcol & 127) >> 1;
                    #pragma unroll
                    for (int rsel = 0; rsel < 2; ++rsel) {
                        const int row = rlo + rsel * 8;
                        const float2 cs = rope[(size_t)(row & (Sn-1)) * 64 + d];
                        float e = rsel ? v0b : v0a, o = rsel ? v1b : v1a;
                        float r0 = e * cs.x - o * cs.y;
                        float r1 = e * cs.y + o * cs.x;
                        ((uint32_t*)KF)[((size_t)row * 512 + kcol) >> 1] = pack_h2(r0, r1);
                    }
                } else {                        // V: plain fp16
                    const int vcol = col - 2560;
                    ((uint32_t*)VF)[((size_t)rlo * 512 + vcol) >> 1]       = pack_h2(v0a, v1a);
                    ((uint32_t*)VF)[((size_t)(rlo + 8) * 512 + vcol) >> 1] = pack_h2(v0b, v1b);
                }
            }
        }
    }
}

// ---------------------------------------------------------------------------
// Flash attention: Q/K/V single fp16, register P, h2exp2 softmax (MUFU halved).
// Block: q-tile 128, 8 warps, j-tiles of 64. SMEM 104448 -> 2 CTAs/SM.
// ---------------------------------------------------------------------------
#define ATT_SMEM 104448

__global__ __launch_bounds__(256, 2)
void attn_mma(const __half* __restrict__ qf,
              const __half* __restrict__ kf, const __half* __restrict__ vf,
              __half* __restrict__ of)
{
    extern __shared__ char smem[];
    const uint32_t sb = smem_to_u32(smem);
    const int tid = threadIdx.x, lane = tid & 31, wq = tid >> 5;
    const int i0 = blockIdx.x * 128;
    const int h  = blockIdx.y, b = blockIdx.z, kvh = h >> 2;

    for (int c = tid; c < 2048; c += 256) {
        int r = c >> 4, ch = c & 15;
        uint32_t dst = sb + r * 272 + ch * 16;
        size_t src = (size_t)(b * Sn + i0 + r) * (NQ * HD) + h * HD + ch * 8;
        cpa16(dst, qf + src);
    }
    CP_COMMIT();

    int jt0 = i0 - WINDOW; if (jt0 < 0) jt0 = 0;
    const int ntiles = (i0 + 64 - jt0) / 64 + 1;

    auto stage_kv = [&](int t, int buf) {
        int jt = jt0 + t * 64;
        uint32_t s0 = sb + 34816 + buf * 34816;
        for (int c = tid; c < 1024; c += 256) {
            int r = c >> 4, ch = c & 15;
            uint32_t dst = s0 + r * 272 + ch * 16;
            size_t src = (size_t)(b * Sn + jt + r) * (NKV * HD) + kvh * HD + ch * 8;
            cpa16(dst,         kf + src);
            cpa16(dst + 17408, vf + src);
        }
        CP_COMMIT();
    };

    stage_kv(0, 0);

    const int g = lane >> 2, t4 = lane & 3;
    const int a_r  = ((lane >> 3) & 1) * 8 + (lane & 7);
    const int a_c8 = (lane >> 4) & 1;
    const int w0 = i0 + wq * 16;

    float m_r[2] = {-1e30f, -1e30f};
    float l_r[2] = {0.f, 0.f};
    float o_acc[16][4];
    #pragma unroll
    for (int nb = 0; nb < 16; ++nb)
        #pragma unroll
        for (int c = 0; c < 4; ++c) o_acc[nb][c] = 0.f;

    for (int t = 0; t < ntiles; ++t) {
        const int buf = t & 1;
        if (t + 1 < ntiles) { stage_kv(t + 1, buf ^ 1); CP_WAIT1(); }
        else                { CP_WAIT0(); }
        __syncthreads();

        const int jt = jt0 + t * 64;
        const bool active = (jt <= w0 + 15) && (jt + 63 >= w0 - WINDOW);

        if (active) {
            const uint32_t sQf = sb;
            const uint32_t sKf = sb + 34816 + buf * 34816;
            const uint32_t sVf = sKf + 17408;

            float s_c[8][4];
            #pragma unroll
            for (int nb = 0; nb < 8; ++nb)
                #pragma unroll
                for (int c = 0; c < 4; ++c) s_c[nb][c] = 0.f;

            #pragma unroll
            for (int ks = 0; ks < 8; ++ks) {
                uint32_t aq[4];
                uint32_t qoff = (uint32_t)((wq * 16 + a_r) * 272 + (ks * 16 + a_c8 * 8) * 2);
                ldsm4(aq, sQf + qoff);
                #pragma unroll
                for (int p = 0; p < 4; ++p) {
                    uint32_t bk[4];
                    uint32_t koff = (uint32_t)((p * 16 + a_r) * 272 + (ks * 16 + a_c8 * 8) * 2);
                    ldsm4(bk, sKf + koff);
                    uint32_t b0[2] = {bk[0], bk[2]}, b1[2] = {bk[1], bk[3]};
                    hmma16(s_c[2*p],   aq, b0);
                    hmma16(s_c[2*p+1], aq, b1);
                }
            }

            const bool need_mask = (jt + 63 > w0) || (w0 + 15 - jt > WINDOW);
            float mt[2] = {-1e30f, -1e30f};
            if (need_mask) {
                #pragma unroll
                for (int nb = 0; nb < 8; ++nb) {
                    const int jbase = jt + nb * 8 + t4 * 2;
                    #pragma unroll
                    for (int c = 0; c < 4; ++c) {
                        const int rr = c >> 1;
                        const int i = w0 + g + rr * 8;
                        const int j = jbase + (c & 1);
                        if (!((j <= i) && (i - j <= WINDOW)))
                            s_c[nb][c] = -1e30f;
                        mt[rr] = fmaxf(mt[rr], s_c[nb][c]);
                    }
                }
            } else {
                #pragma unroll
                for (int nb = 0; nb < 8; ++nb)
                    #pragma unroll
                    for (int c = 0; c < 4; ++c)
                        mt[c >> 1] = fmaxf(mt[c >> 1], s_c[nb][c]);
            }
            float corr[2];
            #pragma unroll
            for (int rr = 0; rr < 2; ++rr) {
                mt[rr] = fmaxf(mt[rr], __shfl_xor_sync(0xffffffffu, mt[rr], 1));
                mt[rr] = fmaxf(mt[rr], __shfl_xor_sync(0xffffffffu, mt[rr], 2));
                float mn = fmaxf(m_r[rr], mt[rr]);
                corr[rr] = exp2f(m_r[rr] - mn);
                m_r[rr] = mn;
            }

            // p = 2^(s-m) via ex2.approx.f16x2 — halves MUFU ops and the
            // result IS the packed half2 PV fragment. l summed in fp32 from
            // the SAME quantized halves (numerator/denominator consistent).
            float ps[2] = {0.f, 0.f};
            uint32_t ph[8][2];
            #pragma unroll
            for (int nb = 0; nb < 8; ++nb) {
                __half2 a0 = h2exp2(__floats2half2_rn(s_c[nb][0] - m_r[0],
                                                      s_c[nb][1] - m_r[0]));
                __half2 a1 = h2exp2(__floats2half2_rn(s_c[nb][2] - m_r[1],
                                                      s_c[nb][3] - m_r[1]));
                ph[nb][0] = *(uint32_t*)&a0;
                ph[nb][1] = *(uint32_t*)&a1;
                float2 f0 = __half22float2(a0);
                float2 f1 = __half22float2(a1);
                ps[0] += f0.x + f0.y;
                ps[1] += f1.x + f1.y;
            }
            #pragma unroll
            for (int rr = 0; rr < 2; ++rr) {
                ps[rr] += __shfl_xor_sync(0xffffffffu, ps[rr], 1);
                ps[rr] += __shfl_xor_sync(0xffffffffu, ps[rr], 2);
                l_r[rr] = l_r[rr] * corr[rr] + ps[rr];
            }
            #pragma unroll
            for (int nb = 0; nb < 16; ++nb) {
                o_acc[nb][0] *= corr[0]; o_acc[nb][1] *= corr[0];
                o_acc[nb][2] *= corr[1]; o_acc[nb][3] *= corr[1];
            }

            #pragma unroll
            for (int ks = 0; ks < 4; ++ks) {
                uint32_t ap[4];
                ap[0] = ph[2*ks][0];
                ap[1] = ph[2*ks][1];
                ap[2] = ph[2*ks+1][0];
                ap[3] = ph[2*ks+1][1];
                #pragma unroll
                for (int p2 = 0; p2 < 8; ++p2) {
                    uint32_t bv[4];
                    uint32_t voff = (uint32_t)((ks * 16 + a_r) * 272 + (p2 * 16 + a_c8 * 8) * 2);
                    ldsm4t(bv, sVf + voff);
                    uint32_t b0[2] = {bv[0], bv[1]}, b1[2] = {bv[2], bv[3]};
                    hmma16(o_acc[2*p2],   ap, b0);
                    hmma16(o_acc[2*p2+1], ap, b1);
                }
            }
        }
        __syncthreads();
    }

    const float inv0 = 1.0f / l_r[0], inv1 = 1.0f / l_r[1];
    #pragma unroll
    for (int nb = 0; nb < 16; ++nb) {
        const int d = nb * 8 + t4 * 2;
        #pragma unroll
        for (int rr = 0; rr < 2; ++rr) {
            const int i = w0 + g + rr * 8;
            const float inv = rr ? inv1 : inv0;
            __half2 hv = __floats2half2_rn(o_acc[nb][rr*2] * inv, o_acc[nb][rr*2+1] * inv);
            const size_t o32 = ((size_t)(b * Sn + i) * NQ + h) * 64 + (d >> 1);
            ((uint32_t*)of)[o32] = *(uint32_t*)&hv;
        }
    }
}

// ---------------------------------------------------------------------------
extern "C" void kernel_launch(void* const* d_in, const int* in_sizes, int n_in,
                              void* d_out, int out_size)
{
    const float* x  = (const float*)d_in[0];
    const float* Wq = (const float*)d_in[1];
    const float* bq = (const float*)d_in[2];
    const float* Wk = (const float*)d_in[3];
    const float* bk = (const float*)d_in[4];
    const float* Wv = (const float*)d_in[5];
    const float* bv = (const float*)d_in[6];
    const float* Wo = (const float*)d_in[7];
    const float* bo = (const float*)d_in[8];
    float* out = (float*)d_out;

    __half *xf, *of, *wqkv, *wo, *qf16, *kf16, *vf16;
    float *bqkv; float2 *rope;
    cudaGetSymbolAddress((void**)&xf, g_xf);     cudaGetSymbolAddress((void**)&of, g_of);
    cudaGetSymbolAddress((void**)&wqkv, g_wqkv); cudaGetSymbolAddress((void**)&wo, g_wo);
    cudaGetSymbolAddress((void**)&bqkv, g_bqkv); cudaGetSymbolAddress((void**)&rope, g_rope);
    cudaGetSymbolAddress((void**)&qf16, g_qf16);
    cudaGetSymbolAddress((void**)&kf16, g_kf16); cudaGetSymbolAddress((void**)&vf16, g_vf16);

    cudaFuncSetAttribute(gemm_f16<0>, cudaFuncAttributeMaxDynamicSharedMemorySize, GEMM_SMEM);
    cudaFuncSetAttribute(gemm_f16<1>, cudaFuncAttributeMaxDynamicSharedMemorySize, GEMM_SMEM);
    cudaFuncSetAttribute(attn_mma, cudaFuncAttributeMaxDynamicSharedMemorySize, ATT_SMEM);

    // Converts + rope table + bias concat
    const int n4x = Mrows * En / 4;
    cvt_f16<<<n4x / 1024, 1024>>>((const float4*)x, (uint2*)xf, n4x);
    cvt_w<<<dim3(64, 64, 4), dim3(32, 8)>>>(Wq, Wk, Wv, Wo, wqkv, wo);
    build_tbl<<<512, 256>>>(rope, bq, bk, bv, bqkv);

    // Fused QKV projection (rope LUT epilogue)
    gemm_f16<1><<<dim3(24, 32), 256, GEMM_SMEM>>>(xf, wqkv, bqkv, nullptr,
                                                  qf16, kf16, vf16, rope,
                                                  Mrows, 3072, En);

    // Flash attention (fp16, register P, h2exp2 softmax), fp16 output
    attn_mma<<<dim3(Sn/128, NQ, Bn), 256, ATT_SMEM>>>(qf16, kf16, vf16, of);

    // Output projection (fp32 out)
    gemm_f16<0><<<dim3(16, 32), 256, GEMM_SMEM>>>(of, wo, bo, out,
                                                  nullptr, nullptr, nullptr, nullptr,
                                                  Mrows, 2048, En);
}

// round 15
// speedup vs baseline: 1.1272x; 1.0352x over previous
#include <cuda_runtime.h>
#include <cuda_fp16.h>
#include <math.h>
#include <cstdint>

// Problem constants
#define Bn 2
#define Sn 2048
#define En 2048
#define NQ 16
#define NKV 4
#define HD 128
#define WINDOW 512
#define Mrows (Bn*Sn)          // 4096

// ---------------------------------------------------------------------------
// Scratch (device globals; no allocation allowed)
// ---------------------------------------------------------------------------
__device__ __half g_xf[(size_t)Mrows * En];        // x fp16
__device__ __half g_of[(size_t)Mrows * En];        // attention out fp16
__device__ __half g_wqkv[(size_t)3072 * 2048];     // [Wq|Wk|Wv] transposed [N,K]
__device__ __half g_wo[(size_t)2048 * 2048];
__device__ float  g_bqkv[3072];                    // [bq|bk|bv]
__device__ float2 g_rope[(size_t)Sn * 64];         // (cos,sin) per (pos,d)
// attention operands (written directly by GEMM epilogues)
__device__ __half g_qf16[(size_t)Mrows * NQ * HD]; // rope'd, scaled
__device__ __half g_kf16[(size_t)Mrows * NKV * HD];// rope'd
__device__ __half g_vf16[(size_t)Mrows * NKV * HD];

// ---------------------------------------------------------------------------
// PTX helpers
// ---------------------------------------------------------------------------
__device__ __forceinline__ uint32_t smem_to_u32(const void* p) {
    uint32_t a;
    asm("{ .reg .u64 t; cvta.to.shared.u64 t, %1; cvt.u32.u64 %0, t; }" : "=r"(a) : "l"(p));
    return a;
}
__device__ __forceinline__ void ldsm4(uint32_t* r, uint32_t addr) {
    asm volatile("ldmatrix.sync.aligned.m8n8.x4.shared.b16 {%0,%1,%2,%3}, [%4];"
        : "=r"(r[0]), "=r"(r[1]), "=r"(r[2]), "=r"(r[3]) : "r"(addr));
}
__device__ __forceinline__ void ldsm4t(uint32_t* r, uint32_t addr) {
    asm volatile("ldmatrix.sync.aligned.m8n8.x4.trans.shared.b16 {%0,%1,%2,%3}, [%4];"
        : "=r"(r[0]), "=r"(r[1]), "=r"(r[2]), "=r"(r[3]) : "r"(addr));
}
__device__ __forceinline__ void hmma16(float* c, const uint32_t* a, const uint32_t* b) {
    asm volatile("mma.sync.aligned.m16n8k16.row.col.f32.f16.f16.f32 "
        "{%0,%1,%2,%3}, {%4,%5,%6,%7}, {%8,%9}, {%0,%1,%2,%3};"
        : "+f"(c[0]), "+f"(c[1]), "+f"(c[2]), "+f"(c[3])
        : "r"(a[0]), "r"(a[1]), "r"(a[2]), "r"(a[3]), "r"(b[0]), "r"(b[1]));
}
__device__ __forceinline__ void cpa16(uint32_t dst, const void* src) {
    asm volatile("cp.async.cg.shared.global [%0], [%1], 16;" :: "r"(dst), "l"(src));
}
#define CP_COMMIT() asm volatile("cp.async.commit_group;" ::: "memory")
#define CP_WAIT0()  asm volatile("cp.async.wait_group 0;" ::: "memory")
#define CP_WAIT1()  asm volatile("cp.async.wait_group 1;" ::: "memory")

__device__ __forceinline__ uint32_t pack_h2(float a, float b) {
    __half2 v = __floats2half2_rn(a, b);
    return *(uint32_t*)&v;
}

// q scale: (1/sqrt(128)) * log2(e)  — softmax done in exp2 space
#define QSCALE 0.1275174056563446f
#define LOG2_10000 13.287712379549449f

// ---------------------------------------------------------------------------
// Fused prep kernel: one launch does everything independent.
//   z = 0: Wq [2048x2048] transpose -> wqkv[0]        (fp16)
//   z = 1: Wk [2048x512]  transpose -> wqkv+2048*2048
//   z = 2: Wv [2048x512]  transpose -> wqkv+2560*2048
//   z = 3: Wo [2048x2048] transpose -> wo
//   z = 4: x fp32->fp16 convert + rope table + bias concat
// grid (64, 64, 5), block (32, 8)
// ---------------------------------------------------------------------------
__global__ void prep_all(const float* __restrict__ x,
                         const float* __restrict__ Wq, const float* __restrict__ Wk,
                         const float* __restrict__ Wv, const float* __restrict__ Wo,
                         const float* __restrict__ bq, const float* __restrict__ bk,
                         const float* __restrict__ bv,
                         __half* __restrict__ wqkv, __half* __restrict__ wo,
                         __half* __restrict__ xf,
                         float2* __restrict__ tbl, float* __restrict__ bqkv)
{
    const int z = blockIdx.z;
    const int tx = threadIdx.x, ty = threadIdx.y;

    if (z == 4) {
        // ---- x convert (+rope table, +bias) ----
        const int lb = blockIdx.y * 64 + blockIdx.x;        // 0..4095
        const int tid = ty * 32 + tx;                        // 0..255
        const int idx = lb * 256 + tid;                      // 0..1048575
        const float4* in = (const float4*)x;
        uint2* out = (uint2*)xf;
        #pragma unroll
        for (int rep = 0; rep < 2; ++rep) {
            int i = idx + rep * 1048576;                     // n4x = 2097152
            float4 v = in[i];
            __half2 a = __floats2half2_rn(v.x, v.y);
            __half2 b = __floats2half2_rn(v.z, v.w);
            uint2 o; o.x = *(uint32_t*)&a; o.y = *(uint32_t*)&b;
            out[i] = o;
        }
        if (idx < Sn * 64) {
            int d = idx & 63, pos = idx >> 6;
            float freq = exp2f(-((float)(2 * d) / 128.0f) * LOG2_10000);
            float ang = (float)pos * freq;
            tbl[idx] = make_float2(cosf(ang), sinf(ang));
        }
        if (idx < 3072) {
            float b;
            if (idx < 2048) b = bq[idx];
            else if (idx < 2560) b = bk[idx - 2048];
            else b = bv[idx - 2560];
            bqkv[idx] = b;
        }
        return;
    }

    // ---- weight transpose ----
    const float* src; __half* dst; int N;
    if (z == 0)      { src = Wq; dst = wqkv;                       N = 2048; }
    else if (z == 1) { src = Wk; dst = wqkv + (size_t)2048 * 2048; N = 512; }
    else if (z == 2) { src = Wv; dst = wqkv + (size_t)2560 * 2048; N = 512; }
    else             { src = Wo; dst = wo;                          N = 2048; }
    const int n0 = blockIdx.x * 32;
    if (n0 >= N) return;
    const int k0 = blockIdx.y * 32;   // K = 2048 always
    __shared__ float t[32][33];
    #pragma unroll
    for (int j = ty; j < 32; j += 8)
        t[j][tx] = src[(size_t)(k0 + j) * N + n0 + tx];
    __syncthreads();
    #pragma unroll
    for (int j = ty; j < 32; j += 8)
        dst[(size_t)(n0 + j) * 2048 + k0 + tx] = __float2half(t[tx][j]);
}

// ---------------------------------------------------------------------------
// fp16 HMMA GEMM (R13/R14, unchanged): BM=128 BN=128 BK=64, 256 thr,
// 2-stage cp.async, single-barrier loop, 2 CTAs/SM.
//   MODE 0: C fp32 = A@B^T + bias                       (output projection)
//   MODE 1: fused QKV epilogue (rope LUT; regions CTA-uniform by col)
// ---------------------------------------------------------------------------
#define STG 32768
#define GEMM_SMEM (2*STG)

template<int MODE>
__global__ __launch_bounds__(256, 2)
void gemm_f16(const __half* __restrict__ A, const __half* __restrict__ B,
              const float* __restrict__ bias, float* __restrict__ C,
              __half* __restrict__ QF, __half* __restrict__ KF, __half* __restrict__ VF,
              const float2* __restrict__ rope,
              int M, int N, int K)
{
    extern __shared__ char smem[];
    const uint32_t sb = smem_to_u32(smem);
    const int tid = threadIdx.x;
    const int wid = tid >> 5;
    const int lane = tid & 31;
    const int wm = wid >> 1;
    const int wn = wid & 1;
    const int row0 = blockIdx.y * 128;
    const int col0 = blockIdx.x * 128;

    const int ld_row = tid >> 3;
    const int ld_seg = tid & 7;

    float acc[2][8][4];
    #pragma unroll
    for (int a = 0; a < 2; ++a)
        #pragma unroll
        for (int b = 0; b < 8; ++b)
            #pragma unroll
            for (int c = 0; c < 4; ++c) acc[a][b][c] = 0.f;

    const int iters = K >> 6;

    auto issue = [&](int it, int stage) {
        const size_t kk = (size_t)(it << 6) + (ld_seg << 3);
        const uint32_t s0 = sb + stage * STG;
        #pragma unroll
        for (int j = 0; j < 4; ++j) {
            const int row = ld_row + j * 32;
            uint32_t bo = (uint32_t)(row * 128 + ld_seg * 16);
            uint32_t sw = bo ^ ((bo >> 3) & 0x70);
            cpa16(s0 + sw,         A + (size_t)(row0 + row) * K + kk);
            cpa16(s0 + 16384 + sw, B + (size_t)(col0 + row) * K + kk);
        }
        CP_COMMIT();
    };

    issue(0, 0);

    const int sub = lane >> 3;
    const int rr  = lane & 7;
    const int arow[2] = { wm*32 + 0*16 + (sub & 1)*8 + rr,
                          wm*32 + 1*16 + (sub & 1)*8 + rr };
    const int acol = (sub >> 1) * 16;
    const int brow[4] = { wn*64 + 0*16 + (sub >> 1)*8 + rr,
                          wn*64 + 1*16 + (sub >> 1)*8 + rr,
                          wn*64 + 2*16 + (sub >> 1)*8 + rr,
                          wn*64 + 3*16 + (sub >> 1)*8 + rr };
    const int bcol = (sub & 1) * 16;

    for (int it = 0; it < iters; ++it) {
        const int stage = it & 1;
        CP_WAIT0();
        __syncthreads();           // publish loads; also fences WAR for issue below
        if (it + 1 < iters) issue(it + 1, stage ^ 1);

        const uint32_t sA = sb + stage * STG;
        const uint32_t sB = sA + 16384;

        #pragma unroll
        for (int ks = 0; ks < 4; ++ks) {
            uint32_t af[2][4], bf[4][4];
            #pragma unroll
            for (int mi = 0; mi < 2; ++mi) {
                uint32_t off = (uint32_t)(arow[mi] * 128 +
                               ((ks*32 + acol) ^ ((arow[mi] & 7) << 4)));
                ldsm4(af[mi], sA + off);
            }
            #pragma unroll
            for (int p = 0; p < 4; ++p) {
                uint32_t off = (uint32_t)(brow[p] * 128 +
                               ((ks*32 + bcol) ^ ((brow[p] & 7) << 4)));
                ldsm4(bf[p], sB + off);
            }
            #pragma unroll
            for (int mi = 0; mi < 2; ++mi)
                #pragma unroll
                for (int ni = 0; ni < 8; ++ni)
                    hmma16(acc[mi][ni], af[mi], &bf[ni >> 1][(ni & 1) * 2]);
        }
    }

    const int g = lane >> 2, t4 = lane & 3;
    #pragma unroll
    for (int mi = 0; mi < 2; ++mi) {
        const int rlo = row0 + wm*32 + mi*16 + g;
        #pragma unroll
        for (int ni = 0; ni < 8; ++ni) {
            const int col = col0 + wn*64 + ni*8 + 2*t4;   // even
            const float b0 = bias[col], b1 = bias[col + 1];
            float v0a = acc[mi][ni][0] + b0, v1a = acc[mi][ni][1] + b1; // row rlo
            float v0b = acc[mi][ni][2] + b0, v1b = acc[mi][ni][3] + b1; // row rlo+8

            if (MODE == 0) {
                *(float2*)(C + (size_t)rlo * N + col)       = make_float2(v0a, v1a);
                *(float2*)(C + (size_t)(rlo + 8) * N + col) = make_float2(v0b, v1b);
            } else {
                if (col < 2048) {               // Q: rope + scale -> fp16
                    const int d = (col & 127) >> 1;
                    #pragma unroll
                    for (int rsel = 0; rsel < 2; ++rsel) {
                        const int row = rlo + rsel * 8;
                        const float2 cs = rope[(size_t)(row & (Sn-1)) * 64 + d];
                        float e = rsel ? v0b : v0a, o = rsel ? v1b : v1a;
                        float r0 = (e * cs.x - o * cs.y) * QSCALE;
                        float r1 = (e * cs.y + o * cs.x) * QSCALE;
                        ((uint32_t*)QF)[((size_t)row * 2048 + col) >> 1] = pack_h2(r0, r1);
                    }
                } else if (col < 2560) {        // K: rope -> fp16
                    const int kcol = col - 2048;
                    const int d = (kcol & 127) >> 1;
                    #pragma unroll
                    for (int rsel = 0; rsel < 2; ++rsel) {
                        const int row = rlo + rsel * 8;
                        const float2 cs = rope[(size_t)(row & (Sn-1)) * 64 + d];
                        float e = rsel ? v0b : v0a, o = rsel ? v1b : v1a;
                        float r0 = e * cs.x - o * cs.y;
                        float r1 = e * cs.y + o * cs.x;
                        ((uint32_t*)KF)[((size_t)row * 512 + kcol) >> 1] = pack_h2(r0, r1);
                    }
                } else {                        // V: plain fp16
                    const int vcol = col - 2560;
                    ((uint32_t*)VF)[((size_t)rlo * 512 + vcol) >> 1]       = pack_h2(v0a, v1a);
                    ((uint32_t*)VF)[((size_t)(rlo + 8) * 512 + vcol) >> 1] = pack_h2(v0b, v1b);
                }
            }
        }
    }
}

// ---------------------------------------------------------------------------
// Flash attention (R14 math, heavy-blocks-first ordering): Q/K/V single fp16,
// register P, h2exp2 softmax. q-tile 128, 8 warps. SMEM 104448 -> 2 CTAs/SM.
// ---------------------------------------------------------------------------
#define ATT_SMEM 104448

__global__ __launch_bounds__(256, 2)
void attn_mma(const __half* __restrict__ qf,
              const __half* __restrict__ kf, const __half* __restrict__ vf,
              __half* __restrict__ of)
{
    extern __shared__ char smem[];
    const uint32_t sb = smem_to_u32(smem);
    const int tid = threadIdx.x, lane = tid & 31, wq = tid >> 5;
    // Heavy blocks (large i0 -> 10 KV tiles) first; light ramp blocks fill the tail.
    const int i0 = (gridDim.x - 1 - blockIdx.x) * 128;
    const int h  = blockIdx.y, b = blockIdx.z, kvh = h >> 2;

    for (int c = tid; c < 2048; c += 256) {
        int r = c >> 4, ch = c & 15;
        uint32_t dst = sb + r * 272 + ch * 16;
        size_t src = (size_t)(b * Sn + i0 + r) * (NQ * HD) + h * HD + ch * 8;
        cpa16(dst, qf + src);
    }
    CP_COMMIT();

    int jt0 = i0 - WINDOW; if (jt0 < 0) jt0 = 0;
    const int ntiles = (i0 + 64 - jt0) / 64 + 1;

    auto stage_kv = [&](int t, int buf) {
        int jt = jt0 + t * 64;
        uint32_t s0 = sb + 34816 + buf * 34816;
        for (int c = tid; c < 1024; c += 256) {
            int r = c >> 4, ch = c & 15;
            uint32_t dst = s0 + r * 272 + ch * 16;
            size_t src = (size_t)(b * Sn + jt + r) * (NKV * HD) + kvh * HD + ch * 8;
            cpa16(dst,         kf + src);
            cpa16(dst + 17408, vf + src);
        }
        CP_COMMIT();
    };

    stage_kv(0, 0);

    const int g = lane >> 2, t4 = lane & 3;
    const int a_r  = ((lane >> 3) & 1) * 8 + (lane & 7);
    const int a_c8 = (lane >> 4) & 1;
    const int w0 = i0 + wq * 16;

    float m_r[2] = {-1e30f, -1e30f};
    float l_r[2] = {0.f, 0.f};
    float o_acc[16][4];
    #pragma unroll
    for (int nb = 0; nb < 16; ++nb)
        #pragma unroll
        for (int c = 0; c < 4; ++c) o_acc[nb][c] = 0.f;

    for (int t = 0; t < ntiles; ++t) {
        const int buf = t & 1;
        if (t + 1 < ntiles) { stage_kv(t + 1, buf ^ 1); CP_WAIT1(); }
        else                { CP_WAIT0(); }
        __syncthreads();

        const int jt = jt0 + t * 64;
        const bool active = (jt <= w0 + 15) && (jt + 63 >= w0 - WINDOW);

        if (active) {
            const uint32_t sQf = sb;
            const uint32_t sKf = sb + 34816 + buf * 34816;
            const uint32_t sVf = sKf + 17408;

            float s_c[8][4];
            #pragma unroll
            for (int nb = 0; nb < 8; ++nb)
                #pragma unroll
                for (int c = 0; c < 4; ++c) s_c[nb][c] = 0.f;

            #pragma unroll
            for (int ks = 0; ks < 8; ++ks) {
                uint32_t aq[4];
                uint32_t qoff = (uint32_t)((wq * 16 + a_r) * 272 + (ks * 16 + a_c8 * 8) * 2);
                ldsm4(aq, sQf + qoff);
                #pragma unroll
                for (int p = 0; p < 4; ++p) {
                    uint32_t bk[4];
                    uint32_t koff = (uint32_t)((p * 16 + a_r) * 272 + (ks * 16 + a_c8 * 8) * 2);
                    ldsm4(bk, sKf + koff);
                    uint32_t b0[2] = {bk[0], bk[2]}, b1[2] = {bk[1], bk[3]};
                    hmma16(s_c[2*p],   aq, b0);
                    hmma16(s_c[2*p+1], aq, b1);
                }
            }

            const bool need_mask = (jt + 63 > w0) || (w0 + 15 - jt > WINDOW);
            float mt[2] = {-1e30f, -1e30f};
            if (need_mask) {
                #pragma unroll
                for (int nb = 0; nb < 8; ++nb) {
                    const int jbase = jt + nb * 8 + t4 * 2;
                    #pragma unroll
                    for (int c = 0; c < 4; ++c) {
                        const int rr = c >> 1;
                        const int i = w0 + g + rr * 8;
                        const int j = jbase + (c & 1);
                        if (!((j <= i) && (i - j <= WINDOW)))
                            s_c[nb][c] = -1e30f;
                        mt[rr] = fmaxf(mt[rr], s_c[nb][c]);
                    }
                }
            } else {
                #pragma unroll
                for (int nb = 0; nb < 8; ++nb)
                    #pragma unroll
                    for (int c = 0; c < 4; ++c)
                        mt[c >> 1] = fmaxf(mt[c >> 1], s_c[nb][c]);
            }
            float corr[2];
            #pragma unroll
            for (int rr = 0; rr < 2; ++rr) {
                mt[rr] = fmaxf(mt[rr], __shfl_xor_sync(0xffffffffu, mt[rr], 1));
                mt[rr] = fmaxf(mt[rr], __shfl_xor_sync(0xffffffffu, mt[rr], 2));
                float mn = fmaxf(m_r[rr], mt[rr]);
                corr[rr] = exp2f(m_r[rr] - mn);
                m_r[rr] = mn;
            }

            // p = 2^(s-m) via ex2.approx.f16x2; result IS the PV A-fragment.
            float ps[2] = {0.f, 0.f};
            uint32_t ph[8][2];
            #pragma unroll
            for (int nb = 0; nb < 8; ++nb) {
                __half2 a0 = h2exp2(__floats2half2_rn(s_c[nb][0] - m_r[0],
                                                      s_c[nb][1] - m_r[0]));
                __half2 a1 = h2exp2(__floats2half2_rn(s_c[nb][2] - m_r[1],
                                                      s_c[nb][3] - m_r[1]));
                ph[nb][0] = *(uint32_t*)&a0;
                ph[nb][1] = *(uint32_t*)&a1;
                float2 f0 = __half22float2(a0);
                float2 f1 = __half22float2(a1);
                ps[0] += f0.x + f0.y;
                ps[1] += f1.x + f1.y;
            }
            #pragma unroll
            for (int rr = 0; rr < 2; ++rr) {
                ps[rr] += __shfl_xor_sync(0xffffffffu, ps[rr], 1);
                ps[rr] += __shfl_xor_sync(0xffffffffu, ps[rr], 2);
                l_r[rr] = l_r[rr] * corr[rr] + ps[rr];
            }
            #pragma unroll
            for (int nb = 0; nb < 16; ++nb) {
                o_acc[nb][0] *= corr[0]; o_acc[nb][1] *= corr[0];
                o_acc[nb][2] *= corr[1]; o_acc[nb][3] *= corr[1];
            }

            #pragma unroll
            for (int ks = 0; ks < 4; ++ks) {
                uint32_t ap[4];
                ap[0] = ph[2*ks][0];
                ap[1] = ph[2*ks][1];
                ap[2] = ph[2*ks+1][0];
                ap[3] = ph[2*ks+1][1];
                #pragma unroll
                for (int p2 = 0; p2 < 8; ++p2) {
                    uint32_t bv[4];
                    uint32_t voff = (uint32_t)((ks * 16 + a_r) * 272 + (p2 * 16 + a_c8 * 8) * 2);
                    ldsm4t(bv, sVf + voff);
                    uint32_t b0[2] = {bv[0], bv[1]}, b1[2] = {bv[2], bv[3]};
                    hmma16(o_acc[2*p2],   ap, b0);
                    hmma16(o_acc[2*p2+1], ap, b1);
                }
            }
        }
        __syncthreads();
    }

    const float inv0 = 1.0f / l_r[0], inv1 = 1.0f / l_r[1];
    #pragma unroll
    for (int nb = 0; nb < 16; ++nb) {
        const int d = nb * 8 + t4 * 2;
        #pragma unroll
        for (int rr = 0; rr < 2; ++rr) {
            const int i = w0 + g + rr * 8;
            const float inv = rr ? inv1 : inv0;
            __half2 hv = __floats2half2_rn(o_acc[nb][rr*2] * inv, o_acc[nb][rr*2+1] * inv);
            const size_t o32 = ((size_t)(b * Sn + i) * NQ + h) * 64 + (d >> 1);
            ((uint32_t*)of)[o32] = *(uint32_t*)&hv;
        }
    }
}

// ---------------------------------------------------------------------------
extern "C" void kernel_launch(void* const* d_in, const int* in_sizes, int n_in,
                              void* d_out, int out_size)
{
    const float* x  = (const float*)d_in[0];
    const float* Wq = (const float*)d_in[1];
    const float* bq = (const float*)d_in[2];
    const float* Wk = (const float*)d_in[3];
    const float* bk = (const float*)d_in[4];
    const float* Wv = (const float*)d_in[5];
    const float* bv = (const float*)d_in[6];
    const float* Wo = (const float*)d_in[7];
    const float* bo = (const float*)d_in[8];
    float* out = (float*)d_out;

    __half *xf, *of, *wqkv, *wo, *qf16, *kf16, *vf16;
    float *bqkv; float2 *rope;
    cudaGetSymbolAddress((void**)&xf, g_xf);     cudaGetSymbolAddress((void**)&of, g_of);
    cudaGetSymbolAddress((void**)&wqkv, g_wqkv); cudaGetSymbolAddress((void**)&wo, g_wo);
    cudaGetSymbolAddress((void**)&bqkv, g_bqkv); cudaGetSymbolAddress((void**)&rope, g_rope);
    cudaGetSymbolAddress((void**)&qf16, g_qf16);
    cudaGetSymbolAddress((void**)&kf16, g_kf16); cudaGetSymbolAddress((void**)&vf16, g_vf16);

    cudaFuncSetAttribute(gemm_f16<0>, cudaFuncAttributeMaxDynamicSharedMemorySize, GEMM_SMEM);
    cudaFuncSetAttribute(gemm_f16<1>, cudaFuncAttributeMaxDynamicSharedMemorySize, GEMM_SMEM);
    cudaFuncSetAttribute(attn_mma, cudaFuncAttributeMaxDynamicSharedMemorySize, ATT_SMEM);

    // One fused prep launch: x convert + 4 weight transposes + rope table + bias
    prep_all<<<dim3(64, 64, 5), dim3(32, 8)>>>(x, Wq, Wk, Wv, Wo, bq, bk, bv,
                                               wqkv, wo, xf, rope, bqkv);

    // Fused QKV projection (rope LUT epilogue)
    gemm_f16<1><<<dim3(24, 32), 256, GEMM_SMEM>>>(xf, wqkv, bqkv, nullptr,
                                                  qf16, kf16, vf16, rope,
                                                  Mrows, 3072, En);

    // Flash attention (fp16, register P, h2exp2 softmax), fp16 output
    attn_mma<<<dim3(Sn/128, NQ, Bn), 256, ATT_SMEM>>>(qf16, kf16, vf16, of);

    // Output projection (fp32 out)
    gemm_f16<0><<<dim3(16, 32), 256, GEMM_SMEM>>>(of, wo, bo, out,
                                                  nullptr, nullptr, nullptr, nullptr,
                                                  Mrows, 2048, En);
}